// round 4
// baseline (speedup 1.0000x reference)
#include <cuda_runtime.h>
#include <math.h>

// ---------------------------------------------------------------------------
// Problem constants
// ---------------------------------------------------------------------------
#define BATCH   2
#define SEQ     2048
#define FDIM    1024
#define HIDD    1024
#define NHEAD   16
#define DHEAD   64
#define MLPD    4096
#define MROWS   (BATCH*SEQ)      // 4096 token rows

// ---------------------------------------------------------------------------
// Scratch (static device allocations — no cudaMalloc allowed)
// ---------------------------------------------------------------------------
__device__ float g_h   [(size_t)MROWS*FDIM];
__device__ float g_q   [(size_t)MROWS*HIDD];
__device__ float g_k   [(size_t)MROWS*HIDD];
__device__ float g_v   [(size_t)MROWS*HIDD];
__device__ float g_attn[(size_t)MROWS*HIDD];
__device__ float g_res1[(size_t)MROWS*FDIM];
__device__ float g_h2  [(size_t)MROWS*FDIM];
__device__ float g_m1  [(size_t)MROWS*MLPD];

// ---------------------------------------------------------------------------
// LayerNorm: one block per row (F = 1024), 256 threads, float4
// ---------------------------------------------------------------------------
__global__ __launch_bounds__(256) void ln_kernel(
    const float* __restrict__ x, float* __restrict__ y,
    const float* __restrict__ g, const float* __restrict__ b)
{
    const int row  = blockIdx.x;
    const int tid  = threadIdx.x;
    const int lane = tid & 31;
    const int warp = tid >> 5;

    const float4* xr = (const float4*)(x + (size_t)row * FDIM);
    float4 v = xr[tid];

    float s = v.x + v.y + v.z + v.w;
    float q = v.x*v.x + v.y*v.y + v.z*v.z + v.w*v.w;
    #pragma unroll
    for (int off = 16; off; off >>= 1) {
        s += __shfl_xor_sync(0xffffffffu, s, off);
        q += __shfl_xor_sync(0xffffffffu, q, off);
    }
    __shared__ float ss[8], sq[8];
    if (lane == 0) { ss[warp] = s; sq[warp] = q; }
    __syncthreads();
    float ts = 0.f, tq = 0.f;
    #pragma unroll
    for (int i = 0; i < 8; i++) { ts += ss[i]; tq += sq[i]; }

    const float mu  = ts * (1.0f / FDIM);
    const float var = tq * (1.0f / FDIM) - mu * mu;
    const float rs  = rsqrtf(var + 1e-5f);

    float4 gg = ((const float4*)g)[tid];
    float4 bb = ((const float4*)b)[tid];
    float4 o;
    o.x = (v.x - mu) * rs * gg.x + bb.x;
    o.y = (v.y - mu) * rs * gg.y + bb.y;
    o.z = (v.z - mu) * rs * gg.z + bb.z;
    o.w = (v.w - mu) * rs * gg.w + bb.w;
    ((float4*)(y + (size_t)row * FDIM))[tid] = o;
}

// ---------------------------------------------------------------------------
// GEMM: C[M,N] = A[M,K] * B[N,K]^T  (+ fused epilogue)
//   EPI 0: store                      (QKV projections)
//   EPI 1: + bias + resid             (Wo: attn@Wo^T + bo + x)
//   EPI 2: gelu(+bias)                (W1)
//   EPI 3: gelu(+bias) + resid        (W2 + residual2 -> final out)
// 128x128 tile, BK=8, 256 threads, 8x8 microtile
// ---------------------------------------------------------------------------
__device__ __forceinline__ float gelu_exact(float v)
{
    return 0.5f * v * (1.0f + erff(v * 0.70710678118654752f));
}

template<int EPI>
__global__ __launch_bounds__(256) void gemm_tn(
    const float* __restrict__ A, const float* __restrict__ B, float* __restrict__ C,
    int M, int N, int K,
    const float* __restrict__ bias, const float* __restrict__ resid)
{
    __shared__ float As[8][132];   // row stride 132 floats = 528B (16B aligned)
    __shared__ float Bs[8][132];

    const int tid = threadIdx.x;
    const int bm  = blockIdx.y * 128;
    const int bn  = blockIdx.x * 128;

    // loaders: thread -> (row, k-quad)
    const int lr = tid >> 1;          // 0..127
    const int lk = (tid & 1) << 2;    // 0 or 4
    const float* Ald = A + (size_t)(bm + lr) * K + lk;
    const float* Bld = B + (size_t)(bn + lr) * K + lk;

    // compute mapping: 16x16 thread grid, 8x8 microtile
    const int tx = tid & 15;
    const int ty = tid >> 4;

    float acc[8][8];
    #pragma unroll
    for (int i = 0; i < 8; i++)
        #pragma unroll
        for (int j = 0; j < 8; j++) acc[i][j] = 0.f;

    float4 a4 = *(const float4*)Ald;
    float4 b4 = *(const float4*)Bld;

    for (int k0 = 0; k0 < K; k0 += 8) {
        __syncthreads();
        As[lk+0][lr] = a4.x; As[lk+1][lr] = a4.y; As[lk+2][lr] = a4.z; As[lk+3][lr] = a4.w;
        Bs[lk+0][lr] = b4.x; Bs[lk+1][lr] = b4.y; Bs[lk+2][lr] = b4.z; Bs[lk+3][lr] = b4.w;
        __syncthreads();

        if (k0 + 8 < K) {   // prefetch next stage into registers (hides gmem latency)
            a4 = *(const float4*)(Ald + k0 + 8);
            b4 = *(const float4*)(Bld + k0 + 8);
        }

        #pragma unroll
        for (int kk = 0; kk < 8; kk++) {
            float a[8], b[8];
            *(float4*)&a[0] = *(const float4*)&As[kk][ty*8];
            *(float4*)&a[4] = *(const float4*)&As[kk][ty*8 + 4];
            *(float4*)&b[0] = *(const float4*)&Bs[kk][tx*8];
            *(float4*)&b[4] = *(const float4*)&Bs[kk][tx*8 + 4];
            #pragma unroll
            for (int i = 0; i < 8; i++)
                #pragma unroll
                for (int j = 0; j < 8; j++)
                    acc[i][j] += a[i] * b[j];
        }
    }

    // fused epilogue, vectorized stores
    #pragma unroll
    for (int i = 0; i < 8; i++) {
        const size_t row = (size_t)(bm + ty*8 + i);
        #pragma unroll
        for (int j = 0; j < 8; j += 4) {
            const int col = bn + tx*8 + j;
            float4 r;
            r.x = acc[i][j+0]; r.y = acc[i][j+1]; r.z = acc[i][j+2]; r.w = acc[i][j+3];
            if (EPI >= 1) {
                float4 bb = *(const float4*)&bias[col];
                r.x += bb.x; r.y += bb.y; r.z += bb.z; r.w += bb.w;
            }
            if (EPI == 2 || EPI == 3) {
                r.x = gelu_exact(r.x); r.y = gelu_exact(r.y);
                r.z = gelu_exact(r.z); r.w = gelu_exact(r.w);
            }
            if (EPI == 1 || EPI == 3) {
                float4 rr = *(const float4*)&resid[row * N + col];
                r.x += rr.x; r.y += rr.y; r.z += rr.z; r.w += rr.w;
            }
            *(float4*)&C[row * N + col] = r;
        }
    }
}

// ---------------------------------------------------------------------------
// Flash attention (fp32): dh=64, 64-query blocks, 64-key tiles, online softmax
// Grid: (SEQ/64, BATCH*NHEAD), 256 threads (8 warps x 8 query rows each).
// Q/K/V/O layout: [B, N, HID] with head h at column h*64.
// scale = 1/sqrt(HID) = 1/32 folded into Q on load.
// ---------------------------------------------------------------------------
#define FA_SMEM_FLOATS (64*64 + 64*65 + 64*64 + 64*64)   // Qs + Kt + Vs + Ps
#define FA_SMEM_BYTES  (FA_SMEM_FLOATS * 4)

__global__ __launch_bounds__(256) void flash_attn_kernel(
    const float* __restrict__ Q, const float* __restrict__ K,
    const float* __restrict__ V, float* __restrict__ O)
{
    extern __shared__ float sm[];
    float* Qs = sm;                      // [64][64]  Qs[r*64+d]
    float* Kt = sm + 64*64;              // [64][65]  Kt[d*65+c]   (d-major, conflict-free reads)
    float* Vs = Kt + 64*65;              // [64][64]  Vs[c*64+d]
    float* Ps = Vs + 64*64;              // [64][64]  Ps[r*64+c]

    const int tid  = threadIdx.x;
    const int lane = tid & 31;
    const int warp = tid >> 5;
    const int b    = blockIdx.y >> 4;
    const int h    = blockIdx.y & 15;
    const size_t base = ((size_t)b * SEQ) * HIDD + (size_t)h * DHEAD;
    const int q0   = blockIdx.x * 64;
    const int rbase = warp * 8;

    // Load + scale Q tile
    #pragma unroll
    for (int j = 0; j < 4; j++) {
        int idx = tid + j * 256;                 // 1024 float4s
        int r  = idx >> 4;
        int dq = (idx & 15) << 2;
        float4 qv = *(const float4*)(Q + base + (size_t)(q0 + r) * HIDD + dq);
        qv.x *= 0.03125f; qv.y *= 0.03125f; qv.z *= 0.03125f; qv.w *= 0.03125f;
        *(float4*)&Qs[r*64 + dq] = qv;
    }

    float oi[8][2], mi[8], li[8];
    #pragma unroll
    for (int r = 0; r < 8; r++) {
        oi[r][0] = 0.f; oi[r][1] = 0.f; mi[r] = -1e30f; li[r] = 0.f;
    }

    for (int kt = 0; kt < SEQ; kt += 64) {
        __syncthreads();   // protect smem reuse (also makes Qs visible on iter 0)
        #pragma unroll
        for (int j = 0; j < 4; j++) {
            int idx = tid + j * 256;
            int c  = idx >> 4;
            int dq = (idx & 15) << 2;
            size_t g = base + (size_t)(kt + c) * HIDD + dq;
            float4 kv = *(const float4*)(K + g);
            Kt[(dq+0)*65 + c] = kv.x;
            Kt[(dq+1)*65 + c] = kv.y;
            Kt[(dq+2)*65 + c] = kv.z;
            Kt[(dq+3)*65 + c] = kv.w;
            float4 vv = *(const float4*)(V + g);
            *(float4*)&Vs[c*64 + dq] = vv;
        }
        __syncthreads();

        // S = Q*K^T for this warp's 8 rows; lane owns key columns (lane, lane+32)
        float s0[8], s1[8];
        #pragma unroll
        for (int r = 0; r < 8; r++) { s0[r] = 0.f; s1[r] = 0.f; }
        #pragma unroll
        for (int d4 = 0; d4 < 16; d4++) {
            const int dd = d4 << 2;
            const float ka0 = Kt[(dd+0)*65 + lane],      kb0 = Kt[(dd+0)*65 + 32 + lane];
            const float ka1 = Kt[(dd+1)*65 + lane],      kb1 = Kt[(dd+1)*65 + 32 + lane];
            const float ka2 = Kt[(dd+2)*65 + lane],      kb2 = Kt[(dd+2)*65 + 32 + lane];
            const float ka3 = Kt[(dd+3)*65 + lane],      kb3 = Kt[(dd+3)*65 + 32 + lane];
            #pragma unroll
            for (int r = 0; r < 8; r++) {
                float4 qv = *(const float4*)&Qs[(rbase + r)*64 + dd];
                s0[r] += qv.x*ka0 + qv.y*ka1 + qv.z*ka2 + qv.w*ka3;
                s1[r] += qv.x*kb0 + qv.y*kb1 + qv.z*kb2 + qv.w*kb3;
            }
        }

        // online softmax per row
        #pragma unroll
        for (int r = 0; r < 8; r++) {
            float mx = fmaxf(s0[r], s1[r]);
            #pragma unroll
            for (int off = 16; off; off >>= 1)
                mx = fmaxf(mx, __shfl_xor_sync(0xffffffffu, mx, off));
            const float mn    = fmaxf(mi[r], mx);
            const float alpha = __expf(mi[r] - mn);
            const float p0 = __expf(s0[r] - mn);
            const float p1 = __expf(s1[r] - mn);
            float ps = p0 + p1;
            #pragma unroll
            for (int off = 16; off; off >>= 1)
                ps += __shfl_xor_sync(0xffffffffu, ps, off);
            li[r] = li[r] * alpha + ps;
            oi[r][0] *= alpha; oi[r][1] *= alpha;
            mi[r] = mn;
            Ps[(rbase + r)*64 + lane]      = p0;
            Ps[(rbase + r)*64 + 32 + lane] = p1;
        }
        __syncwarp();

        // O += P * V ; lane owns output dims (lane, lane+32); V regs reused over rows
        #pragma unroll
        for (int cq = 0; cq < 16; cq++) {
            const int cc = cq << 2;
            const float va0 = Vs[(cc+0)*64 + lane], vb0 = Vs[(cc+0)*64 + 32 + lane];
            const float va1 = Vs[(cc+1)*64 + lane], vb1 = Vs[(cc+1)*64 + 32 + lane];
            const float va2 = Vs[(cc+2)*64 + lane], vb2 = Vs[(cc+2)*64 + 32 + lane];
            const float va3 = Vs[(cc+3)*64 + lane], vb3 = Vs[(cc+3)*64 + 32 + lane];
            #pragma unroll
            for (int r = 0; r < 8; r++) {
                float4 p = *(const float4*)&Ps[(rbase + r)*64 + cc];
                oi[r][0] += p.x*va0 + p.y*va1 + p.z*va2 + p.w*va3;
                oi[r][1] += p.x*vb0 + p.y*vb1 + p.z*vb2 + p.w*vb3;
            }
        }
    }

    #pragma unroll
    for (int r = 0; r < 8; r++) {
        const float inv = 1.0f / li[r];
        const size_t orow = base + (size_t)(q0 + rbase + r) * HIDD;
        O[orow + lane]      = oi[r][0] * inv;
        O[orow + 32 + lane] = oi[r][1] * inv;
    }
}

// ---------------------------------------------------------------------------
// Launch
// ---------------------------------------------------------------------------
extern "C" void kernel_launch(void* const* d_in, const int* in_sizes, int n_in,
                              void* d_out, int out_size)
{
    const float* x     = (const float*)d_in[0];
    const float* la1_g = (const float*)d_in[1];
    const float* la1_b = (const float*)d_in[2];
    const float* Wq    = (const float*)d_in[3];
    const float* Wk    = (const float*)d_in[4];
    const float* Wv    = (const float*)d_in[5];
    const float* Wo    = (const float*)d_in[6];
    const float* bo    = (const float*)d_in[7];
    const float* la2_g = (const float*)d_in[8];
    const float* la2_b = (const float*)d_in[9];
    const float* W1    = (const float*)d_in[10];
    const float* b1    = (const float*)d_in[11];
    const float* W2    = (const float*)d_in[12];
    const float* b2    = (const float*)d_in[13];
    float* out = (float*)d_out;

    float *h, *q, *k, *v, *attn, *res1, *h2, *m1;
    cudaGetSymbolAddress((void**)&h,    g_h);
    cudaGetSymbolAddress((void**)&q,    g_q);
    cudaGetSymbolAddress((void**)&k,    g_k);
    cudaGetSymbolAddress((void**)&v,    g_v);
    cudaGetSymbolAddress((void**)&attn, g_attn);
    cudaGetSymbolAddress((void**)&res1, g_res1);
    cudaGetSymbolAddress((void**)&h2,   g_h2);
    cudaGetSymbolAddress((void**)&m1,   g_m1);

    // Opt-in dynamic smem (>48KB) for the attention kernel. Sticky per function;
    // first (non-captured) correctness call establishes it.
    cudaFuncSetAttribute(flash_attn_kernel,
                         cudaFuncAttributeMaxDynamicSharedMemorySize, FA_SMEM_BYTES);

    const dim3 blk(256);

    // 1) LN1: x -> h
    ln_kernel<<<MROWS, blk>>>(x, h, la1_g, la1_b);

    // 2) Q/K/V projections: h @ W^T
    {
        dim3 grid(HIDD/128, MROWS/128);
        gemm_tn<0><<<grid, blk>>>(h, Wq, q, MROWS, HIDD, FDIM, nullptr, nullptr);
        gemm_tn<0><<<grid, blk>>>(h, Wk, k, MROWS, HIDD, FDIM, nullptr, nullptr);
        gemm_tn<0><<<grid, blk>>>(h, Wv, v, MROWS, HIDD, FDIM, nullptr, nullptr);
    }

    // 3) attention (softmax(QK^T/32) V) -> attn  [B,N,HID]
    {
        dim3 grid(SEQ/64, BATCH*NHEAD);
        flash_attn_kernel<<<grid, blk, FA_SMEM_BYTES>>>(q, k, v, attn);
    }

    // 4) out = attn @ Wo^T + bo + x  -> res1
    {
        dim3 grid(FDIM/128, MROWS/128);
        gemm_tn<1><<<grid, blk>>>(attn, Wo, res1, MROWS, FDIM, HIDD, bo, x);
    }

    // 5) LN2: res1 -> h2
    ln_kernel<<<MROWS, blk>>>(res1, h2, la2_g, la2_b);

    // 6) m1 = gelu(h2 @ W1^T + b1)
    {
        dim3 grid(MLPD/128, MROWS/128);
        gemm_tn<2><<<grid, blk>>>(h2, W1, m1, MROWS, MLPD, FDIM, b1, nullptr);
    }

    // 7) out = gelu(m1 @ W2^T + b2) + res1
    {
        dim3 grid(FDIM/128, MROWS/128);
        gemm_tn<3><<<grid, blk>>>(m1, W2, out, MROWS, FDIM, MLPD, b2, res1);
    }
}